// round 7
// baseline (speedup 1.0000x reference)
#include <cuda_runtime.h>
#include <cuda_bf16.h>
#include <math_constants.h>
#include <math.h>
#include <cstdint>

#define DIMN 2048
#define BB 2
#define SS 2048
#define HH 16
#define HDD 128
#define MTOT (BB*SS)   // 4096

// ---------------------------------------------------------------------------
// Scratch (alloc-free rule: __device__ globals)
// ---------------------------------------------------------------------------
__device__ float g_qkv[3][(size_t)MTOT * DIMN];   // q, k, v
__device__ float g_att[(size_t)MTOT * DIMN];
__device__ __nv_bfloat16 g_xh[(size_t)MTOT * DIMN];
__device__ __nv_bfloat16 g_xl[(size_t)MTOT * DIMN];
__device__ __nv_bfloat16 g_ath[(size_t)MTOT * DIMN];
__device__ __nv_bfloat16 g_atl[(size_t)MTOT * DIMN];
__device__ __nv_bfloat16 g_wth[4][(size_t)DIMN * DIMN];   // W^T hi, [N][K]
__device__ __nv_bfloat16 g_wtl[4][(size_t)DIMN * DIMN];   // W^T lo

// ---------------------------------------------------------------------------
// PTX helpers (generic sm_80+ features only: cp.async, ldmatrix, mma.sync)
// ---------------------------------------------------------------------------
__device__ __forceinline__ void cp_async16_s(uint32_t s, const void* g) {
    asm volatile("cp.async.cg.shared.global [%0], [%1], 16;\n" :: "r"(s), "l"(g));
}
#define CP_COMMIT() asm volatile("cp.async.commit_group;\n")

__device__ __forceinline__ uint32_t smem_u32(const void* p) {
    uint32_t a;
    asm("{ .reg .u64 t; cvta.to.shared.u64 t, %1; cvt.u32.u64 %0, t; }"
        : "=r"(a) : "l"(p));
    return a;
}

__device__ __forceinline__ void ldsm_x4(uint32_t addr, uint32_t* r) {
    asm volatile("ldmatrix.sync.aligned.m8n8.x4.shared.b16 {%0,%1,%2,%3}, [%4];"
                 : "=r"(r[0]), "=r"(r[1]), "=r"(r[2]), "=r"(r[3]) : "r"(addr));
}
__device__ __forceinline__ void ldsm_x2(uint32_t addr, uint32_t* r) {
    asm volatile("ldmatrix.sync.aligned.m8n8.x2.shared.b16 {%0,%1}, [%2];"
                 : "=r"(r[0]), "=r"(r[1]) : "r"(addr));
}

__device__ __forceinline__ void mma_bf16(float* d, const uint32_t* a,
                                         const uint32_t* b) {
    asm volatile(
        "mma.sync.aligned.m16n8k16.row.col.f32.bf16.bf16.f32 "
        "{%0,%1,%2,%3}, {%4,%5,%6,%7}, {%8,%9}, {%0,%1,%2,%3};"
        : "+f"(d[0]), "+f"(d[1]), "+f"(d[2]), "+f"(d[3])
        : "r"(a[0]), "r"(a[1]), "r"(a[2]), "r"(a[3]), "r"(b[0]), "r"(b[1]));
}

// ---------------------------------------------------------------------------
// Prep kernel 1: split fp32 rows into bf16 hi/lo (same layout)
// ---------------------------------------------------------------------------
__global__ void split_rows(const float* __restrict__ in,
                           __nv_bfloat16* __restrict__ h,
                           __nv_bfloat16* __restrict__ l) {
    size_t i = ((size_t)blockIdx.x * 256 + threadIdx.x) * 4;
    float4 v = *(const float4*)(in + i);
    __nv_bfloat16 h0 = __float2bfloat16(v.x), h1 = __float2bfloat16(v.y);
    __nv_bfloat16 h2 = __float2bfloat16(v.z), h3 = __float2bfloat16(v.w);
    __nv_bfloat16 l0 = __float2bfloat16(v.x - __bfloat162float(h0));
    __nv_bfloat16 l1 = __float2bfloat16(v.y - __bfloat162float(h1));
    __nv_bfloat16 l2 = __float2bfloat16(v.z - __bfloat162float(h2));
    __nv_bfloat16 l3 = __float2bfloat16(v.w - __bfloat162float(h3));
    *(__nv_bfloat162*)(h + i)     = __nv_bfloat162(h0, h1);
    *(__nv_bfloat162*)(h + i + 2) = __nv_bfloat162(h2, h3);
    *(__nv_bfloat162*)(l + i)     = __nv_bfloat162(l0, l1);
    *(__nv_bfloat162*)(l + i + 2) = __nv_bfloat162(l2, l3);
}

// ---------------------------------------------------------------------------
// Prep kernel 2: transpose W [K,N] -> W^T [N,K] and split into bf16 hi/lo
// ---------------------------------------------------------------------------
__global__ void split_transpose(const float* __restrict__ W,
                                __nv_bfloat16* __restrict__ th,
                                __nv_bfloat16* __restrict__ tl) {
    __shared__ float ts[32][33];
    const int bx = blockIdx.x * 32, by = blockIdx.y * 32;
    const int tx = threadIdx.x, ty = threadIdx.y;   // 32 x 8
    #pragma unroll
    for (int j = 0; j < 4; j++)
        ts[ty + 8 * j][tx] = W[(size_t)(by + ty + 8 * j) * DIMN + bx + tx];
    __syncthreads();
    #pragma unroll
    for (int j = 0; j < 4; j++) {
        float v = ts[tx][ty + 8 * j];
        __nv_bfloat16 h = __float2bfloat16(v);
        __nv_bfloat16 l = __float2bfloat16(v - __bfloat162float(h));
        size_t o = (size_t)(bx + ty + 8 * j) * DIMN + by + tx;
        th[o] = h;
        tl[o] = l;
    }
}

// ---------------------------------------------------------------------------
// bf16 3-term split GEMM on mma.sync.m16n8k16:
// C[M, n_mats*2048]: A[M,K] @ B^T, B is [n_mats*2048][K] K-major contiguous.
// Output matrix j ([M][2048]) lives at C + j*MTOT*DIMN.
// Tile 128x128x32, 256 threads, warp 64x32, double-buffered cp.async,
// 2 CTAs/SM via __launch_bounds__(256, 2).
// ---------------------------------------------------------------------------
#define BKT 32
#define ROWB 80                       // bytes per padded smem row (32 bf16 + 8 pad)
#define ASTRIDE (128 * ROWB)          // 10240 B per array
#define STG_BYTES (4 * ASTRIDE)       // Ah, Al, Bh, Bl
#define GSMEM (2 * STG_BYTES)         // 81920 B

__device__ __forceinline__ void fill_stage(uint32_t stg,
        const __nv_bfloat16* ah, const __nv_bfloat16* al,
        const __nv_bfloat16* bh, const __nv_bfloat16* bl,
        int k0, int t) {
    #pragma unroll
    for (int i = 0; i < 2; i++) {
        int c = t + (i << 8);              // 0..511
        int row = c >> 2, cc = c & 3;
        uint32_t so = (uint32_t)(row * ROWB + cc * 16);
        size_t g = (size_t)row * DIMN + k0 + cc * 8;
        cp_async16_s(stg + so,               ah + g);
        cp_async16_s(stg + ASTRIDE + so,     al + g);
        cp_async16_s(stg + 2 * ASTRIDE + so, bh + g);
        cp_async16_s(stg + 3 * ASTRIDE + so, bl + g);
    }
}

__global__ __launch_bounds__(256, 2)
void hgemm3(const __nv_bfloat16* __restrict__ Ah, const __nv_bfloat16* __restrict__ Al,
            const __nv_bfloat16* __restrict__ Bh, const __nv_bfloat16* __restrict__ Bl,
            float* __restrict__ C) {
    extern __shared__ char dsm[];
    const uint32_t base = smem_u32(dsm);

    const int t    = threadIdx.x;
    const int lane = t & 31;
    const int warp = t >> 5;
    const int wm   = warp >> 2;           // 0..1 -> m offset 64*wm
    const int wn   = warp & 3;            // 0..3 -> n offset 32*wn
    const int bm   = blockIdx.y << 7;
    const int bn   = blockIdx.x << 7;     // global column across n_mats*2048

    const __nv_bfloat16* ah0 = Ah + (size_t)bm * DIMN;
    const __nv_bfloat16* al0 = Al + (size_t)bm * DIMN;
    const __nv_bfloat16* bh0 = Bh + (size_t)bn * DIMN;
    const __nv_bfloat16* bl0 = Bl + (size_t)bn * DIMN;

    // output: matrix index and local column
    const int mat  = bn >> 11;
    const int nloc = bn & 2047;
    float* Cm = C + (size_t)mat * MTOT * DIMN;

    float acc[4][4][4];
    #pragma unroll
    for (int mi = 0; mi < 4; mi++)
        #pragma unroll
        for (int ni = 0; ni < 4; ni++)
            #pragma unroll
            for (int e = 0; e < 4; e++) acc[mi][ni][e] = 0.f;

    const uint32_t a_lrow  = (uint32_t)(lane & 15);
    const uint32_t a_khalf = (uint32_t)(lane >> 4) * 16;
    const uint32_t b_lrow  = (uint32_t)(lane & 7);
    const uint32_t b_khalf = (uint32_t)((lane >> 3) & 1) * 16;

    fill_stage(base, ah0, al0, bh0, bl0, 0, t);
    CP_COMMIT();

    const int NT = DIMN / BKT;   // 64
    for (int kt = 0; kt < NT; kt++) {
        const uint32_t stg = base + (uint32_t)(kt & 1) * STG_BYTES;
        if (kt + 1 < NT) {
            fill_stage(base + (uint32_t)((kt + 1) & 1) * STG_BYTES,
                       ah0, al0, bh0, bl0, (kt + 1) * BKT, t);
            CP_COMMIT();
            asm volatile("cp.async.wait_group 1;\n");
        } else {
            asm volatile("cp.async.wait_group 0;\n");
        }
        __syncthreads();

        const uint32_t As_h = stg;
        const uint32_t As_l = stg + ASTRIDE;
        const uint32_t Bs_h = stg + 2 * ASTRIDE;
        const uint32_t Bs_l = stg + 3 * ASTRIDE;

        #pragma unroll
        for (int ks = 0; ks < 2; ks++) {
            const uint32_t kb = (uint32_t)ks * 32;
            // load all B fragments first (16 regs live)
            uint32_t Bfh[4][2], Bfl[4][2];
            #pragma unroll
            for (int ni = 0; ni < 4; ni++) {
                uint32_t ro = (uint32_t)(wn * 32 + ni * 8) + b_lrow;
                uint32_t off = ro * ROWB + kb + b_khalf;
                ldsm_x2(Bs_h + off, Bfh[ni]);
                ldsm_x2(Bs_l + off, Bfl[ni]);
            }
            // stream A fragments per mi (8 regs live at a time)
            #pragma unroll
            for (int mi = 0; mi < 4; mi++) {
                uint32_t ro = (uint32_t)(wm * 64 + mi * 16) + a_lrow;
                uint32_t off = ro * ROWB + kb + a_khalf;
                uint32_t Afh[4], Afl[4];
                ldsm_x4(As_h + off, Afh);
                ldsm_x4(As_l + off, Afl);
                #pragma unroll
                for (int ni = 0; ni < 4; ni++) {
                    mma_bf16(acc[mi][ni], Afh, Bfh[ni]);
                    mma_bf16(acc[mi][ni], Afl, Bfh[ni]);
                    mma_bf16(acc[mi][ni], Afh, Bfl[ni]);
                }
            }
        }
        __syncthreads();
    }

    // epilogue: thread: c0,c1 at (gr, 2tg), c2,c3 at (gr+8, 2tg)
    const int gr = lane >> 2, tg = lane & 3;
    #pragma unroll
    for (int mi = 0; mi < 4; mi++) {
        #pragma unroll
        for (int ni = 0; ni < 4; ni++) {
            const int m = bm + wm * 64 + mi * 16 + gr;
            const int n = nloc + wn * 32 + ni * 8 + tg * 2;
            *(float2*)(Cm + (size_t)m * DIMN + n) =
                make_float2(acc[mi][ni][0], acc[mi][ni][1]);
            *(float2*)(Cm + (size_t)(m + 8) * DIMN + n) =
                make_float2(acc[mi][ni][2], acc[mi][ni][3]);
        }
    }
}

// ---------------------------------------------------------------------------
// RoPE on q and k, layout [B*S, DIM]. Adjacent-pair rotation.
// ---------------------------------------------------------------------------
__global__ void rope_kernel(float* __restrict__ q, float* __restrict__ k) {
    int idx = blockIdx.x * blockDim.x + threadIdx.x;   // pair index
    int pair = idx & (DIMN / 2 - 1);
    int row  = idx >> 10;
    int s    = row & (SS - 1);
    int dp   = pair & (HDD / 2 - 1);

    float inv = powf(10000.0f, -(float)dp * (1.0f / 64.0f));
    float ang = (float)s * inv;
    float sn, cs;
    sincosf(ang, &sn, &cs);

    size_t bse = (size_t)row * DIMN + 2 * pair;
    float2 qe = *(float2*)(q + bse);
    *(float2*)(q + bse) = make_float2(qe.x * cs - qe.y * sn, qe.x * sn + qe.y * cs);
    float2 ke = *(float2*)(k + bse);
    *(float2*)(k + bse) = make_float2(ke.x * cs - ke.y * sn, ke.x * sn + ke.y * cs);
}

// ---------------------------------------------------------------------------
// Flash attention, causal, BM=BN=64, HD=128, 256 threads (fp32).
// ---------------------------------------------------------------------------
#define FLASH_SMEM ((64*129*2 + 64*128 + 64*65) * 4)

__global__ __launch_bounds__(256, 1)
void flash_kernel(const float* __restrict__ Q, const float* __restrict__ K,
                  const float* __restrict__ V, float* __restrict__ O) {
    extern __shared__ float sm[];
    float* Qs = sm;                    // [64][129]
    float* Ks = sm + 64 * 129;         // [64][129]
    float* Vs = Ks + 64 * 129;         // [64][128]
    float* Ss = Vs + 64 * 128;         // [64][65]

    const int t  = threadIdx.x;
    const int qt = blockIdx.x, h = blockIdx.y, b = blockIdx.z;
    const int q0 = qt * 64;
    const float scale = 0.08838834764831845f;   // 1/sqrt(128)

    const float* Qp = Q + ((size_t)b * SS) * DIMN + h * HDD;
    const float* Kp = K + ((size_t)b * SS) * DIMN + h * HDD;
    const float* Vp = V + ((size_t)b * SS) * DIMN + h * HDD;

    for (int i = t; i < 64 * 32; i += 256) {
        int r = i >> 5, c = (i & 31) << 2;
        float4 v4 = *(const float4*)(Qp + (size_t)(q0 + r) * DIMN + c);
        float* dst = Qs + r * 129 + c;
        dst[0] = v4.x; dst[1] = v4.y; dst[2] = v4.z; dst[3] = v4.w;
    }

    const int tmq = t >> 4, tnq = t & 15;
    const int i0 = tmq * 4, j0 = tnq * 4;
    const int r = t >> 2, q4 = t & 3;

    float4 acc[8];
    #pragma unroll
    for (int jj = 0; jj < 8; jj++) acc[jj] = make_float4(0.f, 0.f, 0.f, 0.f);
    float mval = -CUDART_INF_F, lval = 0.f;

    for (int kt = 0; kt <= qt; kt++) {
        const int k0 = kt * 64;
        __syncthreads();
        for (int i = t; i < 64 * 32; i += 256) {
            int rr = i >> 5, c = (i & 31) << 2;
            float4 kv = *(const float4*)(Kp + (size_t)(k0 + rr) * DIMN + c);
            float* kd = Ks + rr * 129 + c;
            kd[0] = kv.x; kd[1] = kv.y; kd[2] = kv.z; kd[3] = kv.w;
            *(float4*)(Vs + rr * 128 + c) =
                *(const float4*)(Vp + (size_t)(k0 + rr) * DIMN + c);
        }
        __syncthreads();

        float cacc[4][4];
        #pragma unroll
        for (int x = 0; x < 4; x++)
            #pragma unroll
            for (int y = 0; y < 4; y++) cacc[x][y] = 0.f;
        #pragma unroll 4
        for (int d = 0; d < 128; d++) {
            float qr[4], kr[4];
            #pragma unroll
            for (int x = 0; x < 4; x++) qr[x] = Qs[(i0 + x) * 129 + d];
            #pragma unroll
            for (int y = 0; y < 4; y++) kr[y] = Ks[(j0 + y) * 129 + d];
            #pragma unroll
            for (int x = 0; x < 4; x++)
                #pragma unroll
                for (int y = 0; y < 4; y++) cacc[x][y] += qr[x] * kr[y];
        }
        #pragma unroll
        for (int x = 0; x < 4; x++) {
            int gi = q0 + i0 + x;
            #pragma unroll
            for (int y = 0; y < 4; y++) {
                int gj = k0 + j0 + y;
                float sv = cacc[x][y] * scale;
                if (gj > gi) sv = -CUDART_INF_F;
                Ss[(i0 + x) * 65 + j0 + y] = sv;
            }
        }
        __syncthreads();

        float* srow = Ss + r * 65;
        float mloc = -CUDART_INF_F;
        #pragma unroll
        for (int j = 0; j < 16; j++) mloc = fmaxf(mloc, srow[q4 * 16 + j]);
        mloc = fmaxf(mloc, __shfl_xor_sync(0xFFFFFFFFu, mloc, 1));
        mloc = fmaxf(mloc, __shfl_xor_sync(0xFFFFFFFFu, mloc, 2));
        float mnew = fmaxf(mval, mloc);
        float corr = __expf(mval - mnew);
        float lloc = 0.f;
        #pragma unroll
        for (int j = 0; j < 16; j++) {
            float p = __expf(srow[q4 * 16 + j] - mnew);
            srow[q4 * 16 + j] = p;
            lloc += p;
        }
        lloc += __shfl_xor_sync(0xFFFFFFFFu, lloc, 1);
        lloc += __shfl_xor_sync(0xFFFFFFFFu, lloc, 2);
        lval = lval * corr + lloc;
        mval = mnew;
        #pragma unroll
        for (int jj = 0; jj < 8; jj++) {
            acc[jj].x *= corr; acc[jj].y *= corr;
            acc[jj].z *= corr; acc[jj].w *= corr;
        }
        __syncwarp();

        for (int kk = 0; kk < 64; kk++) {
            float p = srow[kk];
            const float* vr = Vs + kk * 128 + q4 * 4;
            #pragma unroll
            for (int jj = 0; jj < 8; jj++) {
                float4 vv = *(const float4*)(vr + jj * 16);
                acc[jj].x += p * vv.x; acc[jj].y += p * vv.y;
                acc[jj].z += p * vv.z; acc[jj].w += p * vv.w;
            }
        }
    }

    float invl = 1.f / lval;
    float* orow = O + ((size_t)b * SS + q0 + r) * DIMN + h * HDD + q4 * 4;
    #pragma unroll
    for (int jj = 0; jj < 8; jj++) {
        float4 w = acc[jj];
        w.x *= invl; w.y *= invl; w.z *= invl; w.w *= invl;
        *(float4*)(orow + jj * 16) = w;
    }
}

// ---------------------------------------------------------------------------
extern "C" void kernel_launch(void* const* d_in, const int* in_sizes, int n_in,
                              void* d_out, int out_size) {
    const float* x  = (const float*)d_in[0];
    const float* Wq = (const float*)d_in[1];
    const float* Wk = (const float*)d_in[2];
    const float* Wv = (const float*)d_in[3];
    const float* Wo = (const float*)d_in[4];
    float* out = (float*)d_out;

    float *qkv, *att;
    cudaGetSymbolAddress((void**)&qkv, g_qkv);
    cudaGetSymbolAddress((void**)&att, g_att);
    __nv_bfloat16 *xh, *xl, *ath, *atl, *wth, *wtl;
    cudaGetSymbolAddress((void**)&xh,  g_xh);
    cudaGetSymbolAddress((void**)&xl,  g_xl);
    cudaGetSymbolAddress((void**)&ath, g_ath);
    cudaGetSymbolAddress((void**)&atl, g_atl);
    cudaGetSymbolAddress((void**)&wth, g_wth);
    cudaGetSymbolAddress((void**)&wtl, g_wtl);
    const size_t WSZ = (size_t)DIMN * DIMN;
    const size_t QSZ = (size_t)MTOT * DIMN;
    float* q = qkv;
    float* k = qkv + QSZ;
    float* v = qkv + 2 * QSZ;

    cudaFuncSetAttribute(hgemm3,
                         cudaFuncAttributeMaxDynamicSharedMemorySize, GSMEM);
    cudaFuncSetAttribute(flash_kernel,
                         cudaFuncAttributeMaxDynamicSharedMemorySize, FLASH_SMEM);

    dim3 tg(DIMN / 32, DIMN / 32), tb(32, 8);

    // launches 1-4 (prep); launch 5 = fused QKV GEMM (ncu capture slot)
    split_rows<<<(MTOT * DIMN) / 1024, 256>>>(x, xh, xl);
    split_transpose<<<tg, tb>>>(Wq, wth + 0 * WSZ, wtl + 0 * WSZ);
    split_transpose<<<tg, tb>>>(Wk, wth + 1 * WSZ, wtl + 1 * WSZ);
    split_transpose<<<tg, tb>>>(Wv, wth + 2 * WSZ, wtl + 2 * WSZ);

    dim3 gqkv(3 * DIMN / 128, MTOT / 128);   // (48, 32)
    hgemm3<<<gqkv, 256, GSMEM>>>(xh, xl, wth, wtl, qkv);

    split_transpose<<<tg, tb>>>(Wo, wth + 3 * WSZ, wtl + 3 * WSZ);

    rope_kernel<<<(MTOT * (DIMN / 2)) / 256, 256>>>(q, k);

    flash_kernel<<<dim3(SS / 64, HH, BB), 256, FLASH_SMEM>>>(q, k, v, att);

    split_rows<<<(MTOT * DIMN) / 1024, 256>>>(att, ath, atl);
    dim3 go(DIMN / 128, MTOT / 128);         // (16, 32)
    hgemm3<<<go, 256, GSMEM>>>(ath, atl, wth + 3 * WSZ, wtl + 3 * WSZ, out);
}

// round 8
// speedup vs baseline: 1.5189x; 1.5189x over previous
#include <cuda_runtime.h>
#include <cuda_bf16.h>
#include <math_constants.h>
#include <math.h>
#include <cstdint>

#define DIMN 2048
#define BB 2
#define SS 2048
#define HH 16
#define HDD 128
#define MTOT (BB*SS)   // 4096

// ---------------------------------------------------------------------------
// Scratch (alloc-free rule: __device__ globals)
// ---------------------------------------------------------------------------
__device__ float g_qkv[3][(size_t)MTOT * DIMN];   // q, k, v
__device__ float g_att[(size_t)MTOT * DIMN];
__device__ __nv_bfloat16 g_xh[(size_t)MTOT * DIMN];
__device__ __nv_bfloat16 g_xl[(size_t)MTOT * DIMN];
__device__ __nv_bfloat16 g_ath[(size_t)MTOT * DIMN];
__device__ __nv_bfloat16 g_atl[(size_t)MTOT * DIMN];
__device__ __nv_bfloat16 g_wth[4][(size_t)DIMN * DIMN];   // W^T hi, [N][K]
__device__ __nv_bfloat16 g_wtl[4][(size_t)DIMN * DIMN];   // W^T lo

// ---------------------------------------------------------------------------
// PTX helpers (generic sm_80+ features only: cp.async, ldmatrix, mma.sync)
// ---------------------------------------------------------------------------
__device__ __forceinline__ void cp_async16_s(uint32_t s, const void* g) {
    asm volatile("cp.async.cg.shared.global [%0], [%1], 16;\n" :: "r"(s), "l"(g));
}
#define CP_COMMIT() asm volatile("cp.async.commit_group;\n")

__device__ __forceinline__ uint32_t smem_u32(const void* p) {
    uint32_t a;
    asm("{ .reg .u64 t; cvta.to.shared.u64 t, %1; cvt.u32.u64 %0, t; }"
        : "=r"(a) : "l"(p));
    return a;
}

__device__ __forceinline__ void ldsm_x4(uint32_t addr, uint32_t* r) {
    asm volatile("ldmatrix.sync.aligned.m8n8.x4.shared.b16 {%0,%1,%2,%3}, [%4];"
                 : "=r"(r[0]), "=r"(r[1]), "=r"(r[2]), "=r"(r[3]) : "r"(addr));
}
__device__ __forceinline__ void ldsm_x2(uint32_t addr, uint32_t* r) {
    asm volatile("ldmatrix.sync.aligned.m8n8.x2.shared.b16 {%0,%1}, [%2];"
                 : "=r"(r[0]), "=r"(r[1]) : "r"(addr));
}

__device__ __forceinline__ void mma_bf16(float* d, const uint32_t* a,
                                         const uint32_t* b) {
    asm volatile(
        "mma.sync.aligned.m16n8k16.row.col.f32.bf16.bf16.f32 "
        "{%0,%1,%2,%3}, {%4,%5,%6,%7}, {%8,%9}, {%0,%1,%2,%3};"
        : "+f"(d[0]), "+f"(d[1]), "+f"(d[2]), "+f"(d[3])
        : "r"(a[0]), "r"(a[1]), "r"(a[2]), "r"(a[3]), "r"(b[0]), "r"(b[1]));
}

// ---------------------------------------------------------------------------
// Prep kernel 1: split fp32 rows into bf16 hi/lo (same layout)
// ---------------------------------------------------------------------------
__global__ void split_rows(const float* __restrict__ in,
                           __nv_bfloat16* __restrict__ h,
                           __nv_bfloat16* __restrict__ l) {
    size_t i = ((size_t)blockIdx.x * 256 + threadIdx.x) * 4;
    float4 v = *(const float4*)(in + i);
    __nv_bfloat16 h0 = __float2bfloat16(v.x), h1 = __float2bfloat16(v.y);
    __nv_bfloat16 h2 = __float2bfloat16(v.z), h3 = __float2bfloat16(v.w);
    __nv_bfloat16 l0 = __float2bfloat16(v.x - __bfloat162float(h0));
    __nv_bfloat16 l1 = __float2bfloat16(v.y - __bfloat162float(h1));
    __nv_bfloat16 l2 = __float2bfloat16(v.z - __bfloat162float(h2));
    __nv_bfloat16 l3 = __float2bfloat16(v.w - __bfloat162float(h3));
    *(__nv_bfloat162*)(h + i)     = __nv_bfloat162(h0, h1);
    *(__nv_bfloat162*)(h + i + 2) = __nv_bfloat162(h2, h3);
    *(__nv_bfloat162*)(l + i)     = __nv_bfloat162(l0, l1);
    *(__nv_bfloat162*)(l + i + 2) = __nv_bfloat162(l2, l3);
}

// ---------------------------------------------------------------------------
// Prep kernel 2: transpose W [K,N] -> W^T [N,K] and split into bf16 hi/lo
// ---------------------------------------------------------------------------
__global__ void split_transpose(const float* __restrict__ W,
                                __nv_bfloat16* __restrict__ th,
                                __nv_bfloat16* __restrict__ tl) {
    __shared__ float ts[32][33];
    const int bx = blockIdx.x * 32, by = blockIdx.y * 32;
    const int tx = threadIdx.x, ty = threadIdx.y;   // 32 x 8
    #pragma unroll
    for (int j = 0; j < 4; j++)
        ts[ty + 8 * j][tx] = W[(size_t)(by + ty + 8 * j) * DIMN + bx + tx];
    __syncthreads();
    #pragma unroll
    for (int j = 0; j < 4; j++) {
        float v = ts[tx][ty + 8 * j];
        __nv_bfloat16 h = __float2bfloat16(v);
        __nv_bfloat16 l = __float2bfloat16(v - __bfloat162float(h));
        size_t o = (size_t)(bx + ty + 8 * j) * DIMN + by + tx;
        th[o] = h;
        tl[o] = l;
    }
}

// ---------------------------------------------------------------------------
// bf16 3-term split GEMM on mma.sync.m16n8k16:
// C[M, n_mats*2048]: A[M,K] @ B^T, B is [n_mats*2048][K] K-major contiguous.
// Output matrix j ([M][2048]) lives at C + j*MTOT*DIMN.
// Tile 128x128x32, 512 threads (16 warps, warp tile 32x32),
// 3-stage cp.async pipeline. ~90 regs/thread, no spills.
// ---------------------------------------------------------------------------
#define BKT 32
#define ROWB 80                       // bytes per padded smem row (32 bf16 + 8 pad)
#define ASTRIDE (128 * ROWB)          // 10240 B per array
#define STG_BYTES (4 * ASTRIDE)       // Ah, Al, Bh, Bl = 40960 B
#define NSTAGE 3
#define GSMEM (NSTAGE * STG_BYTES)    // 122880 B

__device__ __forceinline__ void fill_stage(uint32_t stg,
        const __nv_bfloat16* ah, const __nv_bfloat16* al,
        const __nv_bfloat16* bh, const __nv_bfloat16* bl,
        int k0, int t) {
    // 512 chunks per array, 512 threads: exactly one chunk each
    int row = t >> 2, cc = t & 3;
    uint32_t so = (uint32_t)(row * ROWB + cc * 16);
    size_t g = (size_t)row * DIMN + k0 + cc * 8;
    cp_async16_s(stg + so,               ah + g);
    cp_async16_s(stg + ASTRIDE + so,     al + g);
    cp_async16_s(stg + 2 * ASTRIDE + so, bh + g);
    cp_async16_s(stg + 3 * ASTRIDE + so, bl + g);
}

__global__ __launch_bounds__(512)
void hgemm3(const __nv_bfloat16* __restrict__ Ah, const __nv_bfloat16* __restrict__ Al,
            const __nv_bfloat16* __restrict__ Bh, const __nv_bfloat16* __restrict__ Bl,
            float* __restrict__ C) {
    extern __shared__ char dsm[];
    const uint32_t base = smem_u32(dsm);

    const int t    = threadIdx.x;
    const int lane = t & 31;
    const int warp = t >> 5;              // 0..15
    const int wm   = warp & 3;            // m offset 32*wm
    const int wn   = warp >> 2;           // n offset 32*wn
    const int bm   = blockIdx.y << 7;
    const int bn   = blockIdx.x << 7;     // global column across n_mats*2048

    const __nv_bfloat16* ah0 = Ah + (size_t)bm * DIMN;
    const __nv_bfloat16* al0 = Al + (size_t)bm * DIMN;
    const __nv_bfloat16* bh0 = Bh + (size_t)bn * DIMN;
    const __nv_bfloat16* bl0 = Bl + (size_t)bn * DIMN;

    // output: matrix index and local column
    const int mat  = bn >> 11;
    const int nloc = bn & 2047;
    float* Cm = C + (size_t)mat * MTOT * DIMN;

    float acc[2][4][4];
    #pragma unroll
    for (int mi = 0; mi < 2; mi++)
        #pragma unroll
        for (int ni = 0; ni < 4; ni++)
            #pragma unroll
            for (int e = 0; e < 4; e++) acc[mi][ni][e] = 0.f;

    const uint32_t a_lrow  = (uint32_t)(lane & 15);
    const uint32_t a_khalf = (uint32_t)(lane >> 4) * 16;
    const uint32_t b_lrow  = (uint32_t)(lane & 7);
    const uint32_t b_khalf = (uint32_t)((lane >> 3) & 1) * 16;

    fill_stage(base, ah0, al0, bh0, bl0, 0, t);
    CP_COMMIT();
    fill_stage(base + STG_BYTES, ah0, al0, bh0, bl0, BKT, t);
    CP_COMMIT();

    const int NT = DIMN / BKT;   // 64
    uint32_t sidx = 0;           // stage of kt
    uint32_t fidx = 2;           // stage to fill (kt+2)
    for (int kt = 0; kt < NT; kt++) {
        if (kt + 2 < NT) {
            fill_stage(base + fidx * STG_BYTES, ah0, al0, bh0, bl0,
                       (kt + 2) * BKT, t);
            CP_COMMIT();
            asm volatile("cp.async.wait_group 2;\n");
        } else {
            asm volatile("cp.async.wait_group 0;\n");
        }
        __syncthreads();

        const uint32_t stg  = base + sidx * STG_BYTES;
        const uint32_t As_h = stg;
        const uint32_t As_l = stg + ASTRIDE;
        const uint32_t Bs_h = stg + 2 * ASTRIDE;
        const uint32_t Bs_l = stg + 3 * ASTRIDE;

        #pragma unroll
        for (int ks = 0; ks < 2; ks++) {
            const uint32_t kb = (uint32_t)ks * 32;
            uint32_t Bfh[4][2], Bfl[4][2];
            #pragma unroll
            for (int ni = 0; ni < 4; ni++) {
                uint32_t ro = (uint32_t)(wn * 32 + ni * 8) + b_lrow;
                uint32_t off = ro * ROWB + kb + b_khalf;
                ldsm_x2(Bs_h + off, Bfh[ni]);
                ldsm_x2(Bs_l + off, Bfl[ni]);
            }
            #pragma unroll
            for (int mi = 0; mi < 2; mi++) {
                uint32_t ro = (uint32_t)(wm * 32 + mi * 16) + a_lrow;
                uint32_t off = ro * ROWB + kb + a_khalf;
                uint32_t Afh[4], Afl[4];
                ldsm_x4(As_h + off, Afh);
                ldsm_x4(As_l + off, Afl);
                #pragma unroll
                for (int ni = 0; ni < 4; ni++) {
                    mma_bf16(acc[mi][ni], Afh, Bfh[ni]);
                    mma_bf16(acc[mi][ni], Afl, Bfh[ni]);
                    mma_bf16(acc[mi][ni], Afh, Bfl[ni]);
                }
            }
        }
        __syncthreads();

        sidx = (sidx + 1 == NSTAGE) ? 0 : sidx + 1;
        fidx = (fidx + 1 == NSTAGE) ? 0 : fidx + 1;
    }

    // epilogue: thread: c0,c1 at (gr, 2tg), c2,c3 at (gr+8, 2tg)
    const int gr = lane >> 2, tg = lane & 3;
    #pragma unroll
    for (int mi = 0; mi < 2; mi++) {
        #pragma unroll
        for (int ni = 0; ni < 4; ni++) {
            const int m = bm + wm * 32 + mi * 16 + gr;
            const int n = nloc + wn * 32 + ni * 8 + tg * 2;
            *(float2*)(Cm + (size_t)m * DIMN + n) =
                make_float2(acc[mi][ni][0], acc[mi][ni][1]);
            *(float2*)(Cm + (size_t)(m + 8) * DIMN + n) =
                make_float2(acc[mi][ni][2], acc[mi][ni][3]);
        }
    }
}

// ---------------------------------------------------------------------------
// RoPE on q and k, layout [B*S, DIM]. Adjacent-pair rotation.
// ---------------------------------------------------------------------------
__global__ void rope_kernel(float* __restrict__ q, float* __restrict__ k) {
    int idx = blockIdx.x * blockDim.x + threadIdx.x;   // pair index
    int pair = idx & (DIMN / 2 - 1);
    int row  = idx >> 10;
    int s    = row & (SS - 1);
    int dp   = pair & (HDD / 2 - 1);

    float inv = powf(10000.0f, -(float)dp * (1.0f / 64.0f));
    float ang = (float)s * inv;
    float sn, cs;
    sincosf(ang, &sn, &cs);

    size_t bse = (size_t)row * DIMN + 2 * pair;
    float2 qe = *(float2*)(q + bse);
    *(float2*)(q + bse) = make_float2(qe.x * cs - qe.y * sn, qe.x * sn + qe.y * cs);
    float2 ke = *(float2*)(k + bse);
    *(float2*)(k + bse) = make_float2(ke.x * cs - ke.y * sn, ke.x * sn + ke.y * cs);
}

// ---------------------------------------------------------------------------
// Flash attention, causal, BM=BN=64, HD=128, 256 threads (fp32).
// ---------------------------------------------------------------------------
#define FLASH_SMEM ((64*129*2 + 64*128 + 64*65) * 4)

__global__ __launch_bounds__(256, 1)
void flash_kernel(const float* __restrict__ Q, const float* __restrict__ K,
                  const float* __restrict__ V, float* __restrict__ O) {
    extern __shared__ float sm[];
    float* Qs = sm;                    // [64][129]
    float* Ks = sm + 64 * 129;         // [64][129]
    float* Vs = Ks + 64 * 129;         // [64][128]
    float* Ss = Vs + 64 * 128;         // [64][65]

    const int t  = threadIdx.x;
    const int qt = blockIdx.x, h = blockIdx.y, b = blockIdx.z;
    const int q0 = qt * 64;
    const float scale = 0.08838834764831845f;   // 1/sqrt(128)

    const float* Qp = Q + ((size_t)b * SS) * DIMN + h * HDD;
    const float* Kp = K + ((size_t)b * SS) * DIMN + h * HDD;
    const float* Vp = V + ((size_t)b * SS) * DIMN + h * HDD;

    for (int i = t; i < 64 * 32; i += 256) {
        int r = i >> 5, c = (i & 31) << 2;
        float4 v4 = *(const float4*)(Qp + (size_t)(q0 + r) * DIMN + c);
        float* dst = Qs + r * 129 + c;
        dst[0] = v4.x; dst[1] = v4.y; dst[2] = v4.z; dst[3] = v4.w;
    }

    const int tmq = t >> 4, tnq = t & 15;
    const int i0 = tmq * 4, j0 = tnq * 4;
    const int r = t >> 2, q4 = t & 3;

    float4 acc[8];
    #pragma unroll
    for (int jj = 0; jj < 8; jj++) acc[jj] = make_float4(0.f, 0.f, 0.f, 0.f);
    float mval = -CUDART_INF_F, lval = 0.f;

    for (int kt = 0; kt <= qt; kt++) {
        const int k0 = kt * 64;
        __syncthreads();
        for (int i = t; i < 64 * 32; i += 256) {
            int rr = i >> 5, c = (i & 31) << 2;
            float4 kv = *(const float4*)(Kp + (size_t)(k0 + rr) * DIMN + c);
            float* kd = Ks + rr * 129 + c;
            kd[0] = kv.x; kd[1] = kv.y; kd[2] = kv.z; kd[3] = kv.w;
            *(float4*)(Vs + rr * 128 + c) =
                *(const float4*)(Vp + (size_t)(k0 + rr) * DIMN + c);
        }
        __syncthreads();

        float cacc[4][4];
        #pragma unroll
        for (int x = 0; x < 4; x++)
            #pragma unroll
            for (int y = 0; y < 4; y++) cacc[x][y] = 0.f;
        #pragma unroll 4
        for (int d = 0; d < 128; d++) {
            float qr[4], kr[4];
            #pragma unroll
            for (int x = 0; x < 4; x++) qr[x] = Qs[(i0 + x) * 129 + d];
            #pragma unroll
            for (int y = 0; y < 4; y++) kr[y] = Ks[(j0 + y) * 129 + d];
            #pragma unroll
            for (int x = 0; x < 4; x++)
                #pragma unroll
                for (int y = 0; y < 4; y++) cacc[x][y] += qr[x] * kr[y];
        }
        #pragma unroll
        for (int x = 0; x < 4; x++) {
            int gi = q0 + i0 + x;
            #pragma unroll
            for (int y = 0; y < 4; y++) {
                int gj = k0 + j0 + y;
                float sv = cacc[x][y] * scale;
                if (gj > gi) sv = -CUDART_INF_F;
                Ss[(i0 + x) * 65 + j0 + y] = sv;
            }
        }
        __syncthreads();

        float* srow = Ss + r * 65;
        float mloc = -CUDART_INF_F;
        #pragma unroll
        for (int j = 0; j < 16; j++) mloc = fmaxf(mloc, srow[q4 * 16 + j]);
        mloc = fmaxf(mloc, __shfl_xor_sync(0xFFFFFFFFu, mloc, 1));
        mloc = fmaxf(mloc, __shfl_xor_sync(0xFFFFFFFFu, mloc, 2));
        float mnew = fmaxf(mval, mloc);
        float corr = __expf(mval - mnew);
        float lloc = 0.f;
        #pragma unroll
        for (int j = 0; j < 16; j++) {
            float p = __expf(srow[q4 * 16 + j] - mnew);
            srow[q4 * 16 + j] = p;
            lloc += p;
        }
        lloc += __shfl_xor_sync(0xFFFFFFFFu, lloc, 1);
        lloc += __shfl_xor_sync(0xFFFFFFFFu, lloc, 2);
        lval = lval * corr + lloc;
        mval = mnew;
        #pragma unroll
        for (int jj = 0; jj < 8; jj++) {
            acc[jj].x *= corr; acc[jj].y *= corr;
            acc[jj].z *= corr; acc[jj].w *= corr;
        }
        __syncwarp();

        for (int kk = 0; kk < 64; kk++) {
            float p = srow[kk];
            const float* vr = Vs + kk * 128 + q4 * 4;
            #pragma unroll
            for (int jj = 0; jj < 8; jj++) {
                float4 vv = *(const float4*)(vr + jj * 16);
                acc[jj].x += p * vv.x; acc[jj].y += p * vv.y;
                acc[jj].z += p * vv.z; acc[jj].w += p * vv.w;
            }
        }
    }

    float invl = 1.f / lval;
    float* orow = O + ((size_t)b * SS + q0 + r) * DIMN + h * HDD + q4 * 4;
    #pragma unroll
    for (int jj = 0; jj < 8; jj++) {
        float4 w = acc[jj];
        w.x *= invl; w.y *= invl; w.z *= invl; w.w *= invl;
        *(float4*)(orow + jj * 16) = w;
    }
}

// ---------------------------------------------------------------------------
extern "C" void kernel_launch(void* const* d_in, const int* in_sizes, int n_in,
                              void* d_out, int out_size) {
    const float* x  = (const float*)d_in[0];
    const float* Wq = (const float*)d_in[1];
    const float* Wk = (const float*)d_in[2];
    const float* Wv = (const float*)d_in[3];
    const float* Wo = (const float*)d_in[4];
    float* out = (float*)d_out;

    float *qkv, *att;
    cudaGetSymbolAddress((void**)&qkv, g_qkv);
    cudaGetSymbolAddress((void**)&att, g_att);
    __nv_bfloat16 *xh, *xl, *ath, *atl, *wth, *wtl;
    cudaGetSymbolAddress((void**)&xh,  g_xh);
    cudaGetSymbolAddress((void**)&xl,  g_xl);
    cudaGetSymbolAddress((void**)&ath, g_ath);
    cudaGetSymbolAddress((void**)&atl, g_atl);
    cudaGetSymbolAddress((void**)&wth, g_wth);
    cudaGetSymbolAddress((void**)&wtl, g_wtl);
    const size_t WSZ = (size_t)DIMN * DIMN;
    const size_t QSZ = (size_t)MTOT * DIMN;
    float* q = qkv;
    float* k = qkv + QSZ;
    float* v = qkv + 2 * QSZ;

    cudaFuncSetAttribute(hgemm3,
                         cudaFuncAttributeMaxDynamicSharedMemorySize, GSMEM);
    cudaFuncSetAttribute(flash_kernel,
                         cudaFuncAttributeMaxDynamicSharedMemorySize, FLASH_SMEM);

    dim3 tg(DIMN / 32, DIMN / 32), tb(32, 8);

    split_rows<<<(MTOT * DIMN) / 1024, 256>>>(x, xh, xl);
    split_transpose<<<tg, tb>>>(Wq, wth + 0 * WSZ, wtl + 0 * WSZ);
    split_transpose<<<tg, tb>>>(Wk, wth + 1 * WSZ, wtl + 1 * WSZ);
    split_transpose<<<tg, tb>>>(Wv, wth + 2 * WSZ, wtl + 2 * WSZ);

    dim3 gqkv(3 * DIMN / 128, MTOT / 128);   // (48, 32)
    hgemm3<<<gqkv, 512, GSMEM>>>(xh, xl, wth, wtl, qkv);

    split_transpose<<<tg, tb>>>(Wo, wth + 3 * WSZ, wtl + 3 * WSZ);

    rope_kernel<<<(MTOT * (DIMN / 2)) / 256, 256>>>(q, k);

    flash_kernel<<<dim3(SS / 64, HH, BB), 256, FLASH_SMEM>>>(q, k, v, att);

    split_rows<<<(MTOT * DIMN) / 1024, 256>>>(att, ath, atl);
    dim3 go(DIMN / 128, MTOT / 128);         // (16, 32)
    hgemm3<<<go, 512, GSMEM>>>(ath, atl, wth + 3 * WSZ, wtl + 3 * WSZ, out);
}

// round 9
// speedup vs baseline: 2.5397x; 1.6721x over previous
#include <cuda_runtime.h>
#include <cuda_bf16.h>
#include <math_constants.h>
#include <math.h>
#include <cstdint>

#define DIMN 2048
#define BB 2
#define SS 2048
#define HH 16
#define HDD 128
#define MTOT (BB*SS)   // 4096

// ---------------------------------------------------------------------------
// Scratch (alloc-free rule: __device__ globals)
// ---------------------------------------------------------------------------
__device__ float g_qkv[3][(size_t)MTOT * DIMN];   // q, k, v (fp32)
__device__ float g_att[(size_t)MTOT * DIMN];
__device__ __nv_bfloat16 g_xh[(size_t)MTOT * DIMN];
__device__ __nv_bfloat16 g_xl[(size_t)MTOT * DIMN];
__device__ __nv_bfloat16 g_ath[(size_t)MTOT * DIMN];
__device__ __nv_bfloat16 g_atl[(size_t)MTOT * DIMN];
__device__ __nv_bfloat16 g_wth[4][(size_t)DIMN * DIMN];   // W^T hi, [N][K]
__device__ __nv_bfloat16 g_wtl[4][(size_t)DIMN * DIMN];   // W^T lo
__device__ __nv_bfloat16 g_qh[(size_t)MTOT * DIMN];
__device__ __nv_bfloat16 g_ql[(size_t)MTOT * DIMN];
__device__ __nv_bfloat16 g_kh[(size_t)MTOT * DIMN];
__device__ __nv_bfloat16 g_kl[(size_t)MTOT * DIMN];
__device__ __nv_bfloat16 g_vh[(size_t)MTOT * DIMN];
__device__ __nv_bfloat16 g_vl[(size_t)MTOT * DIMN];

// ---------------------------------------------------------------------------
// PTX helpers (generic sm_80+ features only)
// ---------------------------------------------------------------------------
__device__ __forceinline__ void cp_async16_s(uint32_t s, const void* g) {
    asm volatile("cp.async.cg.shared.global [%0], [%1], 16;\n" :: "r"(s), "l"(g));
}
#define CP_COMMIT() asm volatile("cp.async.commit_group;\n")

__device__ __forceinline__ uint32_t smem_u32(const void* p) {
    uint32_t a;
    asm("{ .reg .u64 t; cvta.to.shared.u64 t, %1; cvt.u32.u64 %0, t; }"
        : "=r"(a) : "l"(p));
    return a;
}

__device__ __forceinline__ void ldsm_x4(uint32_t addr, uint32_t* r) {
    asm volatile("ldmatrix.sync.aligned.m8n8.x4.shared.b16 {%0,%1,%2,%3}, [%4];"
                 : "=r"(r[0]), "=r"(r[1]), "=r"(r[2]), "=r"(r[3]) : "r"(addr));
}
__device__ __forceinline__ void ldsm_x2(uint32_t addr, uint32_t* r) {
    asm volatile("ldmatrix.sync.aligned.m8n8.x2.shared.b16 {%0,%1}, [%2];"
                 : "=r"(r[0]), "=r"(r[1]) : "r"(addr));
}
__device__ __forceinline__ void ldsm_x2_t(uint32_t addr, uint32_t* r) {
    asm volatile("ldmatrix.sync.aligned.m8n8.x2.trans.shared.b16 {%0,%1}, [%2];"
                 : "=r"(r[0]), "=r"(r[1]) : "r"(addr));
}

__device__ __forceinline__ void mma_bf16(float* d, const uint32_t* a,
                                         const uint32_t* b) {
    asm volatile(
        "mma.sync.aligned.m16n8k16.row.col.f32.bf16.bf16.f32 "
        "{%0,%1,%2,%3}, {%4,%5,%6,%7}, {%8,%9}, {%0,%1,%2,%3};"
        : "+f"(d[0]), "+f"(d[1]), "+f"(d[2]), "+f"(d[3])
        : "r"(a[0]), "r"(a[1]), "r"(a[2]), "r"(a[3]), "r"(b[0]), "r"(b[1]));
}

// ---------------------------------------------------------------------------
// Prep: split fp32 rows into bf16 hi/lo
// ---------------------------------------------------------------------------
__global__ void split_rows(const float* __restrict__ in,
                           __nv_bfloat16* __restrict__ h,
                           __nv_bfloat16* __restrict__ l) {
    size_t i = ((size_t)blockIdx.x * 256 + threadIdx.x) * 4;
    float4 v = *(const float4*)(in + i);
    __nv_bfloat16 h0 = __float2bfloat16(v.x), h1 = __float2bfloat16(v.y);
    __nv_bfloat16 h2 = __float2bfloat16(v.z), h3 = __float2bfloat16(v.w);
    __nv_bfloat16 l0 = __float2bfloat16(v.x - __bfloat162float(h0));
    __nv_bfloat16 l1 = __float2bfloat16(v.y - __bfloat162float(h1));
    __nv_bfloat16 l2 = __float2bfloat16(v.z - __bfloat162float(h2));
    __nv_bfloat16 l3 = __float2bfloat16(v.w - __bfloat162float(h3));
    *(__nv_bfloat162*)(h + i)     = __nv_bfloat162(h0, h1);
    *(__nv_bfloat162*)(h + i + 2) = __nv_bfloat162(h2, h3);
    *(__nv_bfloat162*)(l + i)     = __nv_bfloat162(l0, l1);
    *(__nv_bfloat162*)(l + i + 2) = __nv_bfloat162(l2, l3);
}

// ---------------------------------------------------------------------------
// Prep: transpose W -> W^T and split into bf16 hi/lo
// ---------------------------------------------------------------------------
__global__ void split_transpose(const float* __restrict__ W,
                                __nv_bfloat16* __restrict__ th,
                                __nv_bfloat16* __restrict__ tl) {
    __shared__ float ts[32][33];
    const int bx = blockIdx.x * 32, by = blockIdx.y * 32;
    const int tx = threadIdx.x, ty = threadIdx.y;   // 32 x 8
    #pragma unroll
    for (int j = 0; j < 4; j++)
        ts[ty + 8 * j][tx] = W[(size_t)(by + ty + 8 * j) * DIMN + bx + tx];
    __syncthreads();
    #pragma unroll
    for (int j = 0; j < 4; j++) {
        float v = ts[tx][ty + 8 * j];
        __nv_bfloat16 h = __float2bfloat16(v);
        __nv_bfloat16 l = __float2bfloat16(v - __bfloat162float(h));
        size_t o = (size_t)(bx + ty + 8 * j) * DIMN + by + tx;
        th[o] = h;
        tl[o] = l;
    }
}

// ---------------------------------------------------------------------------
// bf16 3-term split GEMM (unchanged from round 8): 128x128x32, 512 thr, 3-stage
// ---------------------------------------------------------------------------
#define BKT 32
#define ROWB 80
#define ASTRIDE (128 * ROWB)
#define STG_BYTES (4 * ASTRIDE)
#define NSTAGE 3
#define GSMEM (NSTAGE * STG_BYTES)

__device__ __forceinline__ void fill_stage(uint32_t stg,
        const __nv_bfloat16* ah, const __nv_bfloat16* al,
        const __nv_bfloat16* bh, const __nv_bfloat16* bl,
        int k0, int t) {
    int row = t >> 2, cc = t & 3;
    uint32_t so = (uint32_t)(row * ROWB + cc * 16);
    size_t g = (size_t)row * DIMN + k0 + cc * 8;
    cp_async16_s(stg + so,               ah + g);
    cp_async16_s(stg + ASTRIDE + so,     al + g);
    cp_async16_s(stg + 2 * ASTRIDE + so, bh + g);
    cp_async16_s(stg + 3 * ASTRIDE + so, bl + g);
}

__global__ __launch_bounds__(512)
void hgemm3(const __nv_bfloat16* __restrict__ Ah, const __nv_bfloat16* __restrict__ Al,
            const __nv_bfloat16* __restrict__ Bh, const __nv_bfloat16* __restrict__ Bl,
            float* __restrict__ C) {
    extern __shared__ char dsm[];
    const uint32_t base = smem_u32(dsm);

    const int t    = threadIdx.x;
    const int lane = t & 31;
    const int warp = t >> 5;
    const int wm   = warp & 3;
    const int wn   = warp >> 2;
    const int bm   = blockIdx.y << 7;
    const int bn   = blockIdx.x << 7;

    const __nv_bfloat16* ah0 = Ah + (size_t)bm * DIMN;
    const __nv_bfloat16* al0 = Al + (size_t)bm * DIMN;
    const __nv_bfloat16* bh0 = Bh + (size_t)bn * DIMN;
    const __nv_bfloat16* bl0 = Bl + (size_t)bn * DIMN;

    const int mat  = bn >> 11;
    const int nloc = bn & 2047;
    float* Cm = C + (size_t)mat * MTOT * DIMN;

    float acc[2][4][4];
    #pragma unroll
    for (int mi = 0; mi < 2; mi++)
        #pragma unroll
        for (int ni = 0; ni < 4; ni++)
            #pragma unroll
            for (int e = 0; e < 4; e++) acc[mi][ni][e] = 0.f;

    const uint32_t a_lrow  = (uint32_t)(lane & 15);
    const uint32_t a_khalf = (uint32_t)(lane >> 4) * 16;
    const uint32_t b_lrow  = (uint32_t)(lane & 7);
    const uint32_t b_khalf = (uint32_t)((lane >> 3) & 1) * 16;

    fill_stage(base, ah0, al0, bh0, bl0, 0, t);
    CP_COMMIT();
    fill_stage(base + STG_BYTES, ah0, al0, bh0, bl0, BKT, t);
    CP_COMMIT();

    const int NT = DIMN / BKT;
    uint32_t sidx = 0, fidx = 2;
    for (int kt = 0; kt < NT; kt++) {
        if (kt + 2 < NT) {
            fill_stage(base + fidx * STG_BYTES, ah0, al0, bh0, bl0,
                       (kt + 2) * BKT, t);
            CP_COMMIT();
            asm volatile("cp.async.wait_group 2;\n");
        } else {
            asm volatile("cp.async.wait_group 0;\n");
        }
        __syncthreads();

        const uint32_t stg  = base + sidx * STG_BYTES;
        const uint32_t As_h = stg;
        const uint32_t As_l = stg + ASTRIDE;
        const uint32_t Bs_h = stg + 2 * ASTRIDE;
        const uint32_t Bs_l = stg + 3 * ASTRIDE;

        #pragma unroll
        for (int ks = 0; ks < 2; ks++) {
            const uint32_t kb = (uint32_t)ks * 32;
            uint32_t Bfh[4][2], Bfl[4][2];
            #pragma unroll
            for (int ni = 0; ni < 4; ni++) {
                uint32_t ro = (uint32_t)(wn * 32 + ni * 8) + b_lrow;
                uint32_t off = ro * ROWB + kb + b_khalf;
                ldsm_x2(Bs_h + off, Bfh[ni]);
                ldsm_x2(Bs_l + off, Bfl[ni]);
            }
            #pragma unroll
            for (int mi = 0; mi < 2; mi++) {
                uint32_t ro = (uint32_t)(wm * 32 + mi * 16) + a_lrow;
                uint32_t off = ro * ROWB + kb + a_khalf;
                uint32_t Afh[4], Afl[4];
                ldsm_x4(As_h + off, Afh);
                ldsm_x4(As_l + off, Afl);
                #pragma unroll
                for (int ni = 0; ni < 4; ni++) {
                    mma_bf16(acc[mi][ni], Afh, Bfh[ni]);
                    mma_bf16(acc[mi][ni], Afl, Bfh[ni]);
                    mma_bf16(acc[mi][ni], Afh, Bfl[ni]);
                }
            }
        }
        __syncthreads();

        sidx = (sidx + 1 == NSTAGE) ? 0 : sidx + 1;
        fidx = (fidx + 1 == NSTAGE) ? 0 : fidx + 1;
    }

    const int gr = lane >> 2, tg = lane & 3;
    #pragma unroll
    for (int mi = 0; mi < 2; mi++) {
        #pragma unroll
        for (int ni = 0; ni < 4; ni++) {
            const int m = bm + wm * 32 + mi * 16 + gr;
            const int n = nloc + wn * 32 + ni * 8 + tg * 2;
            *(float2*)(Cm + (size_t)m * DIMN + n) =
                make_float2(acc[mi][ni][0], acc[mi][ni][1]);
            *(float2*)(Cm + (size_t)(m + 8) * DIMN + n) =
                make_float2(acc[mi][ni][2], acc[mi][ni][3]);
        }
    }
}

// ---------------------------------------------------------------------------
// RoPE + split: read fp32 q/k, rotate, write bf16 hi/lo pairs
// ---------------------------------------------------------------------------
__global__ void rope_split(const float* __restrict__ q, const float* __restrict__ k,
                           __nv_bfloat16* __restrict__ qh, __nv_bfloat16* __restrict__ ql,
                           __nv_bfloat16* __restrict__ kh, __nv_bfloat16* __restrict__ kl) {
    int idx = blockIdx.x * blockDim.x + threadIdx.x;   // pair index
    int pair = idx & (DIMN / 2 - 1);
    int row  = idx >> 10;
    int s    = row & (SS - 1);
    int dp   = pair & (HDD / 2 - 1);

    float inv = powf(10000.0f, -(float)dp * (1.0f / 64.0f));
    float ang = (float)s * inv;
    float sn, cs;
    sincosf(ang, &sn, &cs);

    size_t bse = (size_t)row * DIMN + 2 * pair;
    float2 qe = *(const float2*)(q + bse);
    float qx = qe.x * cs - qe.y * sn, qy = qe.x * sn + qe.y * cs;
    float2 ke = *(const float2*)(k + bse);
    float kx = ke.x * cs - ke.y * sn, ky = ke.x * sn + ke.y * cs;

    __nv_bfloat16 qxh = __float2bfloat16(qx), qyh = __float2bfloat16(qy);
    __nv_bfloat16 kxh = __float2bfloat16(kx), kyh = __float2bfloat16(ky);
    *(__nv_bfloat162*)(qh + bse) = __nv_bfloat162(qxh, qyh);
    *(__nv_bfloat162*)(ql + bse) = __nv_bfloat162(
        __float2bfloat16(qx - __bfloat162float(qxh)),
        __float2bfloat16(qy - __bfloat162float(qyh)));
    *(__nv_bfloat162*)(kh + bse) = __nv_bfloat162(kxh, kyh);
    *(__nv_bfloat162*)(kl + bse) = __nv_bfloat162(
        __float2bfloat16(kx - __bfloat162float(kxh)),
        __float2bfloat16(ky - __bfloat162float(kyh)));
}

// ---------------------------------------------------------------------------
// flash2: tensor-core causal flash attention, BM=BN=64, 256 threads.
// QK^T: mma bf16 3-term (warp tile 16x32). Softmax: fp32 smem + quad shuffles,
// emits P as bf16 hi/lo. P@V: mma bf16 3-term (warp tile 16x64, V via
// ldmatrix.trans). Out accs persist in registers, corr rescale via smem.
// ---------------------------------------------------------------------------
#define FRB 272                 // Q/K/V smem row bytes (128 bf16 + 8 pad)
#define PRB 144                 // P smem row bytes (64 bf16 + 8 pad)
#define SST 66                  // Ss fp32 stride
#define OFF_QH 0
#define OFF_QL 17408
#define OFF_KH 34816
#define OFF_KL 52224
#define OFF_VH 69632
#define OFF_VL 87040
#define OFF_SSX 104448
#define OFF_PH 121344
#define OFF_PL 130560
#define OFF_CORR 139776
#define OFF_LINV 140032
#define FLASH2_SMEM 140288

__global__ __launch_bounds__(256, 1)
void flash2(const __nv_bfloat16* __restrict__ Qh, const __nv_bfloat16* __restrict__ Ql,
            const __nv_bfloat16* __restrict__ Kh, const __nv_bfloat16* __restrict__ Kl,
            const __nv_bfloat16* __restrict__ Vh, const __nv_bfloat16* __restrict__ Vl,
            float* __restrict__ O) {
    extern __shared__ char fsm[];
    const uint32_t base = smem_u32(fsm);
    float* Ssf    = (float*)(fsm + OFF_SSX);
    float* scorrf = (float*)(fsm + OFF_CORR);
    float* linvf  = (float*)(fsm + OFF_LINV);
    __nv_bfloat16* Psh = (__nv_bfloat16*)(fsm + OFF_PH);
    __nv_bfloat16* Psl = (__nv_bfloat16*)(fsm + OFF_PL);

    const int t = threadIdx.x, lane = t & 31, warp = t >> 5;
    const int qt = blockIdx.x, h = blockIdx.y, b = blockIdx.z;
    const int q0 = qt * 64;
    const float scale = 0.08838834764831845f;   // 1/sqrt(128)

    const size_t hoff = ((size_t)b * SS) * DIMN + (size_t)h * HDD;
    const __nv_bfloat16* qh = Qh + hoff;
    const __nv_bfloat16* ql = Ql + hoff;
    const __nv_bfloat16* kh = Kh + hoff;
    const __nv_bfloat16* kl = Kl + hoff;
    const __nv_bfloat16* vh = Vh + hoff;
    const __nv_bfloat16* vl = Vl + hoff;
    float* Op = O + hoff;

    // Q tile load (once)
    #pragma unroll
    for (int i = 0; i < 4; i++) {
        int c = t + (i << 8);
        int row = c >> 4, cc = c & 15;
        uint32_t so = (uint32_t)(row * FRB + cc * 16);
        size_t g = (size_t)(q0 + row) * DIMN + cc * 8;
        cp_async16_s(base + OFF_QH + so, qh + g);
        cp_async16_s(base + OFF_QL + so, ql + g);
    }
    CP_COMMIT();

    const int m0  = (warp >> 1) * 16;
    const int n0q = (warp & 1) * 32;
    const int n0p = (warp & 1) * 64;
    const int gr = lane >> 2, tg = lane & 3;
    const int sr = t >> 2, q4 = t & 3;      // softmax row / quad lane

    const uint32_t a_lrow = (uint32_t)(lane & 15);
    const uint32_t a_kh   = (uint32_t)(lane >> 4) * 16;
    const uint32_t b_lrow = (uint32_t)(lane & 7);
    const uint32_t b_kh   = (uint32_t)((lane >> 3) & 1) * 16;

    float oacc[8][4];
    #pragma unroll
    for (int ni = 0; ni < 8; ni++)
        #pragma unroll
        for (int e = 0; e < 4; e++) oacc[ni][e] = 0.f;
    float mval = -CUDART_INF_F, lval = 0.f;

    for (int kt = 0; kt <= qt; kt++) {
        const int k0 = kt * 64;
        __syncthreads();   // prior-iter K/V/P consumers done
        #pragma unroll
        for (int i = 0; i < 4; i++) {
            int c = t + (i << 8);
            int row = c >> 4, cc = c & 15;
            uint32_t so = (uint32_t)(row * FRB + cc * 16);
            size_t g = (size_t)(k0 + row) * DIMN + cc * 8;
            cp_async16_s(base + OFF_KH + so, kh + g);
            cp_async16_s(base + OFF_KL + so, kl + g);
            cp_async16_s(base + OFF_VH + so, vh + g);
            cp_async16_s(base + OFF_VL + so, vl + g);
        }
        CP_COMMIT();
        asm volatile("cp.async.wait_group 0;\n");
        __syncthreads();

        // ---- QK^T (3-term) ----
        float sacc[4][4];
        #pragma unroll
        for (int ni = 0; ni < 4; ni++)
            #pragma unroll
            for (int e = 0; e < 4; e++) sacc[ni][e] = 0.f;
        #pragma unroll
        for (int ks = 0; ks < 8; ks++) {
            const uint32_t kb = (uint32_t)ks * 32;
            uint32_t aoff = (uint32_t)(m0 + a_lrow) * FRB + kb + a_kh;
            uint32_t Afh[4], Afl[4];
            ldsm_x4(base + OFF_QH + aoff, Afh);
            ldsm_x4(base + OFF_QL + aoff, Afl);
            #pragma unroll
            for (int ni = 0; ni < 4; ni++) {
                uint32_t boff = (uint32_t)(n0q + ni * 8 + b_lrow) * FRB + kb + b_kh;
                uint32_t Bfh[2], Bfl[2];
                ldsm_x2(base + OFF_KH + boff, Bfh);
                ldsm_x2(base + OFF_KL + boff, Bfl);
                mma_bf16(sacc[ni], Afh, Bfh);
                mma_bf16(sacc[ni], Afl, Bfh);
                mma_bf16(sacc[ni], Afh, Bfl);
            }
        }
        // mask + write scores
        #pragma unroll
        for (int ni = 0; ni < 4; ni++) {
            int cn = n0q + ni * 8 + tg * 2;
            int r0 = m0 + gr, r1 = r0 + 8;
            float s0 = sacc[ni][0] * scale, s1 = sacc[ni][1] * scale;
            float s2 = sacc[ni][2] * scale, s3 = sacc[ni][3] * scale;
            if (k0 + cn     > q0 + r0) s0 = -CUDART_INF_F;
            if (k0 + cn + 1 > q0 + r0) s1 = -CUDART_INF_F;
            if (k0 + cn     > q0 + r1) s2 = -CUDART_INF_F;
            if (k0 + cn + 1 > q0 + r1) s3 = -CUDART_INF_F;
            Ssf[r0 * SST + cn]     = s0;
            Ssf[r0 * SST + cn + 1] = s1;
            Ssf[r1 * SST + cn]     = s2;
            Ssf[r1 * SST + cn + 1] = s3;
        }
        __syncthreads();

        // ---- online softmax (quad per row), emit P as bf16 hi/lo ----
        {
            float* srow = Ssf + sr * SST + q4 * 16;
            float mloc = -CUDART_INF_F;
            #pragma unroll
            for (int j = 0; j < 16; j++) mloc = fmaxf(mloc, srow[j]);
            mloc = fmaxf(mloc, __shfl_xor_sync(0xFFFFFFFFu, mloc, 1));
            mloc = fmaxf(mloc, __shfl_xor_sync(0xFFFFFFFFu, mloc, 2));
            float mnew = fmaxf(mval, mloc);
            float corr = __expf(mval - mnew);
            if (q4 == 0) scorrf[sr] = corr;
            __nv_bfloat16* php = Psh + sr * (PRB / 2) + q4 * 16;
            __nv_bfloat16* plp = Psl + sr * (PRB / 2) + q4 * 16;
            float lloc = 0.f;
            #pragma unroll
            for (int j = 0; j < 16; j++) {
                float p = __expf(srow[j] - mnew);
                __nv_bfloat16 ph = __float2bfloat16(p);
                php[j] = ph;
                plp[j] = __float2bfloat16(p - __bfloat162float(ph));
                lloc += p;
            }
            lloc += __shfl_xor_sync(0xFFFFFFFFu, lloc, 1);
            lloc += __shfl_xor_sync(0xFFFFFFFFu, lloc, 2);
            lval = lval * corr + lloc;
            mval = mnew;
        }
        __syncthreads();

        // ---- rescale out accs, then P@V (3-term) ----
        {
            float c0 = scorrf[m0 + gr], c1 = scorrf[m0 + gr + 8];
            #pragma unroll
            for (int ni = 0; ni < 8; ni++) {
                oacc[ni][0] *= c0; oacc[ni][1] *= c0;
                oacc[ni][2] *= c1; oacc[ni][3] *= c1;
            }
        }
        #pragma unroll
        for (int ks = 0; ks < 4; ks++) {
            uint32_t aoff = (uint32_t)(m0 + a_lrow) * PRB + (uint32_t)ks * 32 + a_kh;
            uint32_t Afh[4], Afl[4];
            ldsm_x4(base + OFF_PH + aoff, Afh);
            ldsm_x4(base + OFF_PL + aoff, Afl);
            uint32_t vrow = (uint32_t)(ks * 16) + a_lrow;
            #pragma unroll
            for (int ni = 0; ni < 8; ni++) {
                uint32_t boff = vrow * FRB + (uint32_t)(n0p + ni * 8) * 2;
                uint32_t Bfh[2], Bfl[2];
                ldsm_x2_t(base + OFF_VH + boff, Bfh);
                ldsm_x2_t(base + OFF_VL + boff, Bfl);
                mma_bf16(oacc[ni], Afh, Bfh);
                mma_bf16(oacc[ni], Afl, Bfh);
                mma_bf16(oacc[ni], Afh, Bfl);
            }
        }
    }

    __syncthreads();
    if (q4 == 0) linvf[sr] = 1.f / lval;
    __syncthreads();

    const float i0v = linvf[m0 + gr], i1v = linvf[m0 + gr + 8];
    #pragma unroll
    for (int ni = 0; ni < 8; ni++) {
        int col = n0p + ni * 8 + tg * 2;
        *(float2*)(Op + (size_t)(q0 + m0 + gr) * DIMN + col) =
            make_float2(oacc[ni][0] * i0v, oacc[ni][1] * i0v);
        *(float2*)(Op + (size_t)(q0 + m0 + gr + 8) * DIMN + col) =
            make_float2(oacc[ni][2] * i1v, oacc[ni][3] * i1v);
    }
}

// ---------------------------------------------------------------------------
extern "C" void kernel_launch(void* const* d_in, const int* in_sizes, int n_in,
                              void* d_out, int out_size) {
    const float* x  = (const float*)d_in[0];
    const float* Wq = (const float*)d_in[1];
    const float* Wk = (const float*)d_in[2];
    const float* Wv = (const float*)d_in[3];
    const float* Wo = (const float*)d_in[4];
    float* out = (float*)d_out;

    float *qkv, *att;
    cudaGetSymbolAddress((void**)&qkv, g_qkv);
    cudaGetSymbolAddress((void**)&att, g_att);
    __nv_bfloat16 *xh, *xl, *ath, *atl, *wth, *wtl;
    __nv_bfloat16 *qh, *ql, *kh, *kl, *vh, *vl;
    cudaGetSymbolAddress((void**)&xh,  g_xh);
    cudaGetSymbolAddress((void**)&xl,  g_xl);
    cudaGetSymbolAddress((void**)&ath, g_ath);
    cudaGetSymbolAddress((void**)&atl, g_atl);
    cudaGetSymbolAddress((void**)&wth, g_wth);
    cudaGetSymbolAddress((void**)&wtl, g_wtl);
    cudaGetSymbolAddress((void**)&qh,  g_qh);
    cudaGetSymbolAddress((void**)&ql,  g_ql);
    cudaGetSymbolAddress((void**)&kh,  g_kh);
    cudaGetSymbolAddress((void**)&kl,  g_kl);
    cudaGetSymbolAddress((void**)&vh,  g_vh);
    cudaGetSymbolAddress((void**)&vl,  g_vl);
    const size_t WSZ = (size_t)DIMN * DIMN;
    const size_t QSZ = (size_t)MTOT * DIMN;
    float* q = qkv;
    float* k = qkv + QSZ;
    float* v = qkv + 2 * QSZ;

    cudaFuncSetAttribute(hgemm3,
                         cudaFuncAttributeMaxDynamicSharedMemorySize, GSMEM);
    cudaFuncSetAttribute(flash2,
                         cudaFuncAttributeMaxDynamicSharedMemorySize, FLASH2_SMEM);

    dim3 tg(DIMN / 32, DIMN / 32), tb(32, 8);

    // launches 1-5 prep; #6 = hgemm3 (ncu -s 5 capture slot)
    split_rows<<<(MTOT * DIMN) / 1024, 256>>>(x, xh, xl);
    split_transpose<<<tg, tb>>>(Wq, wth + 0 * WSZ, wtl + 0 * WSZ);
    split_transpose<<<tg, tb>>>(Wk, wth + 1 * WSZ, wtl + 1 * WSZ);
    split_transpose<<<tg, tb>>>(Wv, wth + 2 * WSZ, wtl + 2 * WSZ);
    split_transpose<<<tg, tb>>>(Wo, wth + 3 * WSZ, wtl + 3 * WSZ);

    dim3 gqkv(3 * DIMN / 128, MTOT / 128);   // (48, 32)
    hgemm3<<<gqkv, 512, GSMEM>>>(xh, xl, wth, wtl, qkv);

    rope_split<<<(MTOT * (DIMN / 2)) / 256, 256>>>(q, k, qh, ql, kh, kl);
    split_rows<<<(MTOT * DIMN) / 1024, 256>>>(v, vh, vl);

    flash2<<<dim3(SS / 64, HH, BB), 256, FLASH2_SMEM>>>(qh, ql, kh, kl, vh, vl, att);

    split_rows<<<(MTOT * DIMN) / 1024, 256>>>(att, ath, atl);
    dim3 go(DIMN / 128, MTOT / 128);         // (16, 32)
    hgemm3<<<go, 512, GSMEM>>>(ath, atl, wth + 3 * WSZ, wtl + 3 * WSZ, out);
}